// round 12
// baseline (speedup 1.0000x reference)
#include <cuda_runtime.h>
#include <cstdint>

// Embedding gather: out[i, :] = w[x[i], :]
// x: [N=16384] int32, w: [32000, 1024] f32, out: [N, 1024] f32.
//
// Established across R1-R10:
//  - __stcs evict-first stores keep the w table L2-resident across graph
//    replays (reads -> L2 hits); output L2-pinning is impossible (carveout=0,
//    device-limit changes banned); 64MB writes + 64MB LTS reads are both
//    irreducible -> aggregate memory ceiling ~= 16.8us.
// R11 (final lever): single 16-deep load batch -- ALL 16 gather loads
// (256B/thread) in flight before any store, removing the R10 batch boundary
// where batch-1 loads queued behind batch-0 stores. If neutral, floor
// confirmed.

#define DIM 1024
#define VECS_PER_ROW (DIM / 4)      // 256 float4 per row
#define THREADS 256
#define ROWS_PER_BLOCK 16

__global__ __launch_bounds__(THREADS, 3)
void embed_gather_kernel(const int* __restrict__ x,
                         const float4* __restrict__ w,
                         float4* __restrict__ out,
                         int n_rows)
{
    const int tid = threadIdx.x;              // vec index within row
    const int row0 = blockIdx.x * ROWS_PER_BLOCK;

    if (row0 + ROWS_PER_BLOCK <= n_rows) {
        int idx[ROWS_PER_BLOCK];
#pragma unroll
        for (int r = 0; r < ROWS_PER_BLOCK; r++)
            idx[r] = __ldg(&x[row0 + r]);

        // 16 independent 16B gather loads, all issued before any store.
        float4 v[ROWS_PER_BLOCK];
#pragma unroll
        for (int r = 0; r < ROWS_PER_BLOCK; r++)
            v[r] = __ldg(&w[(size_t)idx[r] * VECS_PER_ROW + tid]);

        // Evict-first streaming stores: never displace w from L2.
#pragma unroll
        for (int r = 0; r < ROWS_PER_BLOCK; r++)
            __stcs(&out[(size_t)(row0 + r) * VECS_PER_ROW + tid], v[r]);
    } else {
        for (int r = 0; r < ROWS_PER_BLOCK; r++) {
            int row = row0 + r;
            if (row < n_rows) {
                int idx = __ldg(&x[row]);
                float4 v = __ldg(&w[(size_t)idx * VECS_PER_ROW + tid]);
                __stcs(&out[(size_t)row * VECS_PER_ROW + tid], v);
            }
        }
    }
}

extern "C" void kernel_launch(void* const* d_in, const int* in_sizes, int n_in,
                              void* d_out, int out_size)
{
    // metadata order: x (int32, B*S = 16384), w (float32, 32000*1024)
    const int* x = (const int*)d_in[0];
    const float4* w = (const float4*)d_in[1];
    float4* out = (float4*)d_out;

    const int n_rows = in_sizes[0];           // 16384
    const int grid = (n_rows + ROWS_PER_BLOCK - 1) / ROWS_PER_BLOCK;

    embed_gather_kernel<<<grid, THREADS>>>(x, w, out, n_rows);
}